// round 8
// baseline (speedup 1.0000x reference)
#include <cuda_runtime.h>
#include <math.h>

#define NN 50000
#define NE 800000
#define E2 850000
#define NB 64
#define SCAN_NBLK 98   // ceil(50000/512)
#define XLS 160        // padded row stride for xl/xr (5 aligned 128B lines)

// ---------------- scratch ----------------
__device__ float g_deg[NN];
__device__ float g_dinv[NN];
__device__ int   g_indeg[NN];
__device__ int   g_off[NN + 1];
__device__ int   g_bsum[128];
__device__ int   g_cur[NN];
__device__ int   g_ssrc[E2];
__device__ float g_snorm[E2];
__device__ float g_h32[NN * 32];
__device__ float g_h1[NN];
__device__ float g_xpn[NN * 36];
__device__ float g_xl[NN * XLS];
__device__ float g_xr[NN * XLS];
__device__ float g_xp2[NN * 132];
__device__ float g_pool[NB * 132];
__device__ float g_cnt[NB];
__device__ float g_W1t[3000 * 256];
__device__ float g_W2t[2998 * 256];
__device__ float g_acc1[NB * 5 * 256];
__device__ float g_acc2[NB * 65 * 256];
__device__ int   g_pos1[NB * 3000];
__device__ int   g_poff1[NB * 6];
__device__ int   g_pos2[NB * 2998];
__device__ int   g_poff2[NB * 66];
__device__ float g_y1[NB * 3872];
__device__ float g_y2[NB * 3872];
__device__ float g_hid[NB * 1024];

// ---------------- init (protein) ----------------
__global__ void k_init() {
    int i = blockIdx.x * blockDim.x + threadIdx.x;
    if (i < NN) { g_deg[i] = 1.0f; g_indeg[i] = 1; }
    if (i < NB * 132) g_pool[i] = 0.0f;
    if (i < NB) g_cnt[i] = 0.0f;
}

__global__ void k_edge_count(const int* __restrict__ ei, const float* __restrict__ w) {
    int e = blockIdx.x * blockDim.x + threadIdx.x;
    if (e >= NE) return;
    int d = ei[NE + e];
    atomicAdd(&g_deg[d], w[e]);
    atomicAdd(&g_indeg[d], 1);
}

__global__ void k_dinv() {
    int i = blockIdx.x * blockDim.x + threadIdx.x;
    if (i < NN) g_dinv[i] = rsqrtf(g_deg[i]);
}

// ---------------- multi-block scan ----------------
__global__ void k_scanA() {
    __shared__ int wsum[16];
    int i = blockIdx.x * 512 + threadIdx.x;
    int lane = threadIdx.x & 31, wid = threadIdx.x >> 5;
    int v = (i < NN) ? g_indeg[i] : 0;
    int x = v;
    #pragma unroll
    for (int off = 1; off < 32; off <<= 1) {
        int t = __shfl_up_sync(0xffffffffu, x, off);
        if (lane >= off) x += t;
    }
    if (lane == 31) wsum[wid] = x;
    __syncthreads();
    if (wid == 0) {
        int s = (lane < 16) ? wsum[lane] : 0;
        #pragma unroll
        for (int off = 1; off < 32; off <<= 1) {
            int t = __shfl_up_sync(0xffffffffu, s, off);
            if (lane >= off) s += t;
        }
        if (lane < 16) wsum[lane] = s;
    }
    __syncthreads();
    int pre = (wid > 0) ? wsum[wid - 1] : 0;
    int incl = x + pre;
    if (i < NN) g_off[i] = incl - v;
    if (threadIdx.x == 511) g_bsum[blockIdx.x] = incl;
}

__global__ void k_scanB() {
    __shared__ int wtot[4];
    int t = threadIdx.x;
    int lane = t & 31, wid = t >> 5;
    int v = (t < SCAN_NBLK) ? g_bsum[t] : 0;
    int x = v;
    #pragma unroll
    for (int off = 1; off < 32; off <<= 1) {
        int tt = __shfl_up_sync(0xffffffffu, x, off);
        if (lane >= off) x += tt;
    }
    if (lane == 31) wtot[wid] = x;
    __syncthreads();
    if (t == 0) {
        int run = 0;
        for (int k = 0; k < 4; k++) { int tmp = wtot[k]; wtot[k] = run; run += tmp; }
        g_off[NN] = run;
    }
    __syncthreads();
    int excl = x - v + wtot[wid];
    if (t < SCAN_NBLK) g_bsum[t] = excl;
}

__global__ void k_scanC() {
    int i = blockIdx.x * blockDim.x + threadIdx.x;
    if (i >= NN) return;
    int val = g_off[i] + g_bsum[i >> 9];
    g_off[i] = val;
    g_cur[i] = val;
}

// ---------------- counting-sort scatter ----------------
__global__ void k_scatter(const int* __restrict__ ei, const float* __restrict__ w) {
    int e = blockIdx.x * blockDim.x + threadIdx.x;
    if (e >= NE) return;
    int s = ei[e], d = ei[NE + e];
    int p = atomicAdd(&g_cur[d], 1);
    g_ssrc[p] = s;
    g_snorm[p] = g_dinv[s] * w[e] * g_dinv[d];
}

__global__ void k_selfloop() {
    int i = blockIdx.x * blockDim.x + threadIdx.x;
    if (i >= NN) return;
    int p = atomicAdd(&g_cur[i], 1);
    g_ssrc[p] = i;
    g_snorm[p] = g_dinv[i] * g_dinv[i];
}

// ---------------- GCN transform ----------------
__global__ void k_gcn_h(const float* __restrict__ x, const float* __restrict__ W) {
    __shared__ float Ws[33 * 33];
    __shared__ float xs[8][33];
    int tx = threadIdx.x, ty = threadIdx.y;
    int tid = ty * 36 + tx;
    for (int i = tid; i < 1089; i += 288) Ws[i] = W[i];
    int n = blockIdx.x * 8 + ty;
    if (n < NN && tx < 33) xs[ty][tx] = x[n * 33 + tx];
    __syncthreads();
    if (n >= NN) return;
    if (tx >= 33) return;
    float a = 0.0f;
    #pragma unroll
    for (int k = 0; k < 33; k++) a += xs[ty][k] * Ws[tx * 33 + k];
    if (tx < 32) g_h32[n * 32 + tx] = a;
    else         g_h1[n] = a;
}

// ---------------- GCN aggregation + relu + BN ----------------
__global__ void k_gcn_agg(const float* __restrict__ gcnb, const float* __restrict__ bm,
                          const float* __restrict__ bv, const float* __restrict__ bw,
                          const float* __restrict__ bb) {
    int d = blockIdx.x * 8 + (threadIdx.x >> 5);
    int lane = threadIdx.x & 31;
    if (d >= NN) return;
    int beg = g_off[d], end = g_off[d + 1];
    float a0 = 0.0f, a1 = 0.0f, b0 = 0.0f, b1 = 0.0f;
    int e = beg;
    for (; e + 2 <= end; e += 2) {
        int sA = g_ssrc[e], sB = g_ssrc[e + 1];
        float nA = g_snorm[e], nB = g_snorm[e + 1];
        a0 += g_h32[sA * 32 + lane] * nA;
        b0 += g_h32[sB * 32 + lane] * nB;
        a1 += g_h1[sA] * nA;
        b1 += g_h1[sB] * nB;
    }
    if (e < end) {
        int sA = g_ssrc[e];
        float nA = g_snorm[e];
        a0 += g_h32[sA * 32 + lane] * nA;
        a1 += g_h1[sA] * nA;
    }
    a0 += b0; a1 += b1;
    float c0 = fmaxf(a0 + gcnb[lane], 0.0f);
    float inv0 = bw[lane] * rsqrtf(bv[lane] + 1e-5f);
    g_xpn[d * 36 + lane] = c0 * inv0 + (bb[lane] - bm[lane] * inv0);
    if (lane == 0) {
        float c1 = fmaxf(a1 + gcnb[32], 0.0f);
        float inv1 = bw[32] * rsqrtf(bv[32] + 1e-5f);
        g_xpn[d * 36 + 32] = c1 * inv1 + (bb[32] - bm[32] * inv1);
        g_xpn[d * 36 + 33] = 0.0f;
        g_xpn[d * 36 + 34] = 0.0f;
        g_xpn[d * 36 + 35] = 0.0f;
    }
}

// ---------------- GAT projections (write padded XLS rows) ----------------
#define LR_NPB 64
__global__ void k_gat_lr(const float* __restrict__ wl, const float* __restrict__ wr) {
    __shared__ float Wsh[2 * 132 * 33];
    __shared__ float xs[8][33];
    int t = threadIdx.x;  // 0..263
    for (int i = t; i < 4356; i += 264) Wsh[i] = wl[i];
    for (int i = t; i < 4356; i += 264) Wsh[4356 + i] = wr[i];
    __syncthreads();
    int c = t % 132, side = t / 132;
    float wreg[33];
    #pragma unroll
    for (int k = 0; k < 33; k++) wreg[k] = Wsh[side * 4356 + c * 33 + k];
    float* outb = side ? g_xr : g_xl;
    int n0 = blockIdx.x * LR_NPB;
    int n1 = min(n0 + LR_NPB, NN);
    for (int nb = n0; nb < n1; nb += 8) {
        __syncthreads();
        {
            int u = t / 33, k = t % 33;
            int n = nb + u;
            xs[u][k] = (n < NN) ? g_xpn[n * 36 + k] : 0.0f;
        }
        __syncthreads();
        #pragma unroll
        for (int u = 0; u < 8; u++) {
            int n = nb + u;
            if (n < n1) {
                float a = 0.0f;
                #pragma unroll
                for (int k = 0; k < 33; k++) a += wreg[k] * xs[u][k];
                outb[(size_t)n * XLS + c] = a;
            }
        }
    }
}

// ---------------- GATv2: plain softmax (scores O(1)), 4 dsts per warp ----------------
__global__ void __launch_bounds__(256) k_gat(const float* __restrict__ att, const float* __restrict__ gb) {
    int lane = threadIdx.x & 31, wid = threadIdx.x >> 5;
    const float4* att4 = (const float4*)att;
    const float4* gb4 = (const float4*)gb;
    float4 z = make_float4(0.f, 0.f, 0.f, 0.f);
    float4 at0 = att4[lane];
    float4 at1 = (lane == 0) ? att4[32] : z;
    int cb = 4 * lane;
    bool hA = cb + 0 < 66, hB = cb + 1 < 66, hC = cb + 2 < 66, hD = cb + 3 < 66;

    int dd[4];
    float4 xr0[4], xr1[4], acc0[4], acc1[4];
    float s0[4], s1[4];
    int beg[4], len[4];
    int maxlen = 0;
    #pragma unroll
    for (int k = 0; k < 4; k++) {
        int d = blockIdx.x * 32 + k * 8 + wid;
        dd[k] = d;
        bool ok = d < NN;
        const float4* xr4 = (const float4*)(g_xr + (size_t)(ok ? d : 0) * XLS);
        xr0[k] = ok ? xr4[lane] : z;
        xr1[k] = (ok && lane == 0) ? xr4[32] : z;
        acc0[k] = z; acc1[k] = z;
        s0[k] = 0.f; s1[k] = 0.f;
        beg[k] = ok ? g_off[d] : 0;
        int e1 = ok ? g_off[d + 1] : 0;
        len[k] = e1 - beg[k];
        maxlen = max(maxlen, len[k]);
    }
    for (int i = 0; i < maxlen; i++) {
        #pragma unroll
        for (int k = 0; k < 4; k++) {
            if (i >= len[k]) continue;   // warp-uniform
            int s = g_ssrc[beg[k] + i];
            const float4* xl4 = (const float4*)(g_xl + (size_t)s * XLS);
            float4 a0 = xl4[lane];
            float4 a1 = (lane == 0) ? xl4[32] : z;
            float p0 = 0.f, p1 = 0.f, v, tt;
            v = a0.x + xr0[k].x; v = v > 0.f ? v : 0.2f * v; tt = v * at0.x; if (hA) p0 += tt; else p1 += tt;
            v = a0.y + xr0[k].y; v = v > 0.f ? v : 0.2f * v; tt = v * at0.y; if (hB) p0 += tt; else p1 += tt;
            v = a0.z + xr0[k].z; v = v > 0.f ? v : 0.2f * v; tt = v * at0.z; if (hC) p0 += tt; else p1 += tt;
            v = a0.w + xr0[k].w; v = v > 0.f ? v : 0.2f * v; tt = v * at0.w; if (hD) p0 += tt; else p1 += tt;
            v = a1.x + xr1[k].x; v = v > 0.f ? v : 0.2f * v; p1 += v * at1.x;
            v = a1.y + xr1[k].y; v = v > 0.f ? v : 0.2f * v; p1 += v * at1.y;
            v = a1.z + xr1[k].z; v = v > 0.f ? v : 0.2f * v; p1 += v * at1.z;
            v = a1.w + xr1[k].w; v = v > 0.f ? v : 0.2f * v; p1 += v * at1.w;
            #pragma unroll
            for (int o = 16; o; o >>= 1) {
                p0 += __shfl_xor_sync(0xffffffffu, p0, o);
                p1 += __shfl_xor_sync(0xffffffffu, p1, o);
            }
            float w0 = __expf(p0), w1 = __expf(p1);
            s0[k] += w0; s1[k] += w1;
            float W0 = hA ? w0 : w1;
            float W1 = hB ? w0 : w1;
            float W2 = hC ? w0 : w1;
            float W3 = hD ? w0 : w1;
            acc0[k].x += W0 * a0.x;
            acc0[k].y += W1 * a0.y;
            acc0[k].z += W2 * a0.z;
            acc0[k].w += W3 * a0.w;
            acc1[k].x += w1 * a1.x;
            acc1[k].y += w1 * a1.y;
            acc1[k].z += w1 * a1.z;
            acc1[k].w += w1 * a1.w;
        }
    }
    float4 gv = gb4[lane];
    float4 gv1 = (lane == 0) ? gb4[32] : z;
    #pragma unroll
    for (int k = 0; k < 4; k++) {
        int d = dd[k];
        if (d >= NN) continue;
        float4 o;
        o.x = fmaxf(acc0[k].x / (hA ? s0[k] : s1[k]) + gv.x, 0.f);
        o.y = fmaxf(acc0[k].y / (hB ? s0[k] : s1[k]) + gv.y, 0.f);
        o.z = fmaxf(acc0[k].z / (hC ? s0[k] : s1[k]) + gv.z, 0.f);
        o.w = fmaxf(acc0[k].w / (hD ? s0[k] : s1[k]) + gv.w, 0.f);
        ((float4*)(g_xp2 + (size_t)d * 132))[lane] = o;
        if (lane == 0) {
            float4 o1;
            o1.x = fmaxf(acc1[k].x / s1[k] + gv1.x, 0.f);
            o1.y = fmaxf(acc1[k].y / s1[k] + gv1.y, 0.f);
            o1.z = fmaxf(acc1[k].z / s1[k] + gv1.z, 0.f);
            o1.w = fmaxf(acc1[k].w / s1[k] + gv1.w, 0.f);
            ((float4*)(g_xp2 + (size_t)d * 132))[32] = o1;
        }
    }
}

// ---------------- mean pool ----------------
__global__ void k_pool(const int* __restrict__ batch) {
    int c = threadIdx.x;  // 0..131
    int start = blockIdx.x * 782;
    int end = min(start + 782, NN);
    if (start >= end) return;
    int cur = batch[start];
    float sum = 0.0f, cnt = 0.0f;
    for (int n = start; n < end; n++) {
        int g = batch[n];
        if (g != cur) {
            atomicAdd(&g_pool[cur * 132 + c], sum);
            if (c == 0) atomicAdd(&g_cnt[cur], cnt);
            sum = 0.0f; cnt = 0.0f; cur = g;
        }
        sum += g_xp2[n * 132 + c];
        cnt += 1.0f;
    }
    atomicAdd(&g_pool[cur * 132 + c], sum);
    if (c == 0) atomicAdd(&g_cnt[cur], cnt);
}

// ---------------- protein MLP head ----------------
__global__ void k_fc1(const float* __restrict__ w, const float* __restrict__ b) {
    int g = blockIdx.x;
    int obase = blockIdx.y * 256;
    __shared__ float m[132];
    if (threadIdx.x < 132) {
        float cnt = fmaxf(g_cnt[g], 1.0f);
        m[threadIdx.x] = g_pool[g * 132 + threadIdx.x] / cnt;
    }
    __syncthreads();
    int wid = threadIdx.x >> 5, lane = threadIdx.x & 31;
    for (int o = obase + wid; o < obase + 256; o += 8) {
        float acc = 0.0f;
        for (int k = lane; k < 132; k += 32) acc += w[o * 132 + k] * m[k];
        #pragma unroll
        for (int off = 16; off; off >>= 1) acc += __shfl_xor_sync(0xffffffffu, acc, off);
        if (lane == 0) g_hid[g * 1024 + o] = fmaxf(acc + b[o], 0.0f);
    }
}

__global__ void k_fc2(const float* __restrict__ w, const float* __restrict__ b, float* __restrict__ out) {
    int g = blockIdx.x;
    int obase = blockIdx.y * 64;
    int wid = threadIdx.x >> 5, lane = threadIdx.x & 31;
    for (int o = obase + wid; o < obase + 64; o += 8) {
        float acc = 0.0f;
        for (int k = lane; k < 1024; k += 32) acc += w[o * 1024 + k] * g_hid[g * 1024 + k];
        #pragma unroll
        for (int off = 16; off; off >>= 1) acc += __shfl_xor_sync(0xffffffffu, acc, off);
        if (lane == 0) out[8192 + g * 128 + o] = acc + b[o];
    }
}

// ---------------- RNA branch ----------------
__global__ void k_transpose(const float* __restrict__ w, int C, int which) {
    float* wt = which ? g_W2t : g_W1t;
    int t = blockIdx.x * blockDim.x + threadIdx.x;
    if (t >= C * 256) return;
    int c = t >> 8, j = t & 255, o = j >> 3, k = j & 7;
    wt[t] = w[o * C * 8 + c * 8 + k];
}

// bucket-sort positions by token per batch; buffers selected INSIDE the kernel
__global__ void k_hist(const int* __restrict__ rna, int C, int V, int which) {
    __shared__ int cnt[66];
    __shared__ int cur[65];
    int* pos = which ? g_pos2 : g_pos1;
    int* poff = which ? g_poff2 : g_poff1;
    int b = blockIdx.x, t = threadIdx.x;  // 128 threads
    for (int i = t; i <= V; i += 128) cnt[i] = 0;
    __syncthreads();
    const int* row = rna + b * C;
    for (int c = t; c < C; c += 128) atomicAdd(&cnt[row[c] + 1], 1);
    __syncthreads();
    if (t == 0) {
        int run = 0;
        for (int v = 0; v <= V; v++) { run += cnt[v]; cnt[v] = run; }
    }
    __syncthreads();
    for (int i = t; i <= V; i += 128) poff[b * (V + 1) + i] = cnt[i];
    if (t < V) cur[t] = cnt[t];
    __syncthreads();
    for (int c = t; c < C; c += 128) {
        int v = row[c];
        int p = atomicAdd(&cur[v], 1);
        pos[b * C + p] = c;
    }
}

// V=5: float4 accumulation over sorted bins, position-chunked, atomic flush
__global__ void k_acc5s() {
    int b = blockIdx.x, zc = blockIdx.y;
    int j4 = threadIdx.x;  // 0..63
    const float4* wt = (const float4*)g_W1t;
    const int* pos = g_pos1 + b * 3000;
    const int* poff = g_poff1 + b * 6;
    int lo = zc * 500, hi = lo + 500;
    float4 z = make_float4(0.f, 0.f, 0.f, 0.f);
    #pragma unroll
    for (int v = 0; v < 5; v++) {
        int p0 = max(poff[v], lo), p1 = min(poff[v + 1], hi);
        if (p0 >= p1) continue;
        float4 aA = z, aB = z;
        int p = p0;
        for (; p + 2 <= p1; p += 2) {
            int c0 = pos[p], c1 = pos[p + 1];
            float4 w0 = wt[c0 * 64 + j4];
            float4 w1 = wt[c1 * 64 + j4];
            aA.x += w0.x; aA.y += w0.y; aA.z += w0.z; aA.w += w0.w;
            aB.x += w1.x; aB.y += w1.y; aB.z += w1.z; aB.w += w1.w;
        }
        if (p < p1) {
            float4 w0 = wt[pos[p] * 64 + j4];
            aA.x += w0.x; aA.y += w0.y; aA.z += w0.z; aA.w += w0.w;
        }
        float* o = g_acc1 + b * 1280 + v * 256 + 4 * j4;
        atomicAdd(o + 0, aA.x + aB.x);
        atomicAdd(o + 1, aA.y + aB.y);
        atomicAdd(o + 2, aA.z + aB.z);
        atomicAdd(o + 3, aA.w + aB.w);
    }
}

// V=65: float4 accumulation over sorted bins, bin-chunked, direct store
__global__ void k_acc65c() {
    int b = blockIdx.x;
    int j4 = threadIdx.x;  // 0..63
    int v0 = blockIdx.z * 17;
    int v1 = min(v0 + 17, 65);
    const float4* wt = (const float4*)g_W2t;
    const int* pos = g_pos2 + b * 2998;
    const int* poff = g_poff2 + b * 66;
    float4* acc = (float4*)g_acc2;
    float4 z = make_float4(0.f, 0.f, 0.f, 0.f);
    for (int v = v0; v < v1; v++) {
        int p0 = poff[v], p1 = poff[v + 1];
        float4 aA = z, aB = z;
        int p = p0;
        for (; p + 2 <= p1; p += 2) {
            int c0 = pos[p], c1 = pos[p + 1];
            float4 w0 = wt[c0 * 64 + j4];
            float4 w1 = wt[c1 * 64 + j4];
            aA.x += w0.x; aA.y += w0.y; aA.z += w0.z; aA.w += w0.w;
            aB.x += w1.x; aB.y += w1.y; aB.z += w1.z; aB.w += w1.w;
        }
        if (p < p1) {
            float4 w0 = wt[pos[p] * 64 + j4];
            aA.x += w0.x; aA.y += w0.y; aA.z += w0.z; aA.w += w0.w;
        }
        float4 r;
        r.x = aA.x + aB.x; r.y = aA.y + aB.y; r.z = aA.z + aB.z; r.w = aA.w + aB.w;
        acc[b * 4160 + v * 64 + j4] = r;
    }
}

__global__ void k_conv(const float* __restrict__ emb, const float* __restrict__ bias, int V, int which) {
    extern __shared__ float sh[];
    const float* acc = which ? g_acc2 : g_acc1;
    float* y = which ? g_y2 : g_y1;
    float* emb_sh = sh;
    float* acc_sh = sh + V * 128;
    int b = blockIdx.x, o = blockIdx.y, t = threadIdx.x;
    for (int i = t; i < V * 128; i += 128) emb_sh[i] = emb[i];
    for (int i = t; i < V * 8; i += 128) {
        int v = i >> 3, k = i & 7;
        acc_sh[i] = acc[b * V * 256 + v * 256 + o * 8 + k];
    }
    __syncthreads();
    if (t < 121) {
        float s = bias[o];
        for (int v = 0; v < V; v++) {
            #pragma unroll
            for (int k = 0; k < 8; k++) s += acc_sh[v * 8 + k] * emb_sh[v * 128 + t + k];
        }
        y[b * 3872 + o * 121 + t] = s;
    }
}

__global__ void k_fc_rna(const float* __restrict__ w, const float* __restrict__ bias, float* __restrict__ out) {
    __shared__ float ys[3872];
    int b = blockIdx.x;
    int obase = blockIdx.y * 32;
    for (int i = threadIdx.x; i < 3872; i += 256)
        ys[i] = 0.5f * (g_y1[b * 3872 + i] + g_y2[b * 3872 + i]);
    __syncthreads();
    int wid = threadIdx.x >> 5, lane = threadIdx.x & 31;
    for (int dcol = obase + wid; dcol < obase + 32; dcol += 8) {
        float acc = 0.0f;
        for (int i = lane; i < 3872; i += 32) acc += w[dcol * 3872 + i] * ys[i];
        #pragma unroll
        for (int off = 16; off; off >>= 1) acc += __shfl_xor_sync(0xffffffffu, acc, off);
        if (lane == 0) out[b * 128 + dcol] = acc + bias[dcol];
    }
}

// ---------------- launch ----------------
extern "C" void kernel_launch(void* const* d_in, const int* in_sizes, int n_in,
                              void* d_out, int out_size) {
    const int*   global_rna = (const int*)d_in[0];
    const int*   local_rna  = (const int*)d_in[1];
    const float* pro_x      = (const float*)d_in[2];
    const int*   ei         = (const int*)d_in[3];
    const float* pw         = (const float*)d_in[4];
    const int*   pb         = (const int*)d_in[5];
    const float* emb1       = (const float*)d_in[6];
    const float* emb2       = (const float*)d_in[7];
    const float* c1w        = (const float*)d_in[8];
    const float* c1b        = (const float*)d_in[9];
    const float* c2w        = (const float*)d_in[10];
    const float* c2b        = (const float*)d_in[11];
    const float* fxw        = (const float*)d_in[12];
    const float* fxb        = (const float*)d_in[13];
    const float* gcnw       = (const float*)d_in[14];
    const float* gcnb       = (const float*)d_in[15];
    const float* bnm        = (const float*)d_in[16];
    const float* bnv        = (const float*)d_in[17];
    const float* bnw        = (const float*)d_in[18];
    const float* bnb        = (const float*)d_in[19];
    const float* gwl        = (const float*)d_in[20];
    const float* gwr        = (const float*)d_in[21];
    const float* gatt       = (const float*)d_in[22];
    const float* gb         = (const float*)d_in[23];
    const float* f1w        = (const float*)d_in[24];
    const float* f1b        = (const float*)d_in[25];
    const float* f2w        = (const float*)d_in[26];
    const float* f2b        = (const float*)d_in[27];
    float* out = (float*)d_out;

    static cudaStream_t sR = nullptr, sC = nullptr;
    static cudaEvent_t evF = nullptr, evJ = nullptr, ev0 = nullptr, evC = nullptr;
    static float* p_acc1 = nullptr;
    if (!sR) {
        cudaStreamCreateWithFlags(&sR, cudaStreamNonBlocking);
        cudaStreamCreateWithFlags(&sC, cudaStreamNonBlocking);
        cudaEventCreateWithFlags(&evF, cudaEventDisableTiming);
        cudaEventCreateWithFlags(&evJ, cudaEventDisableTiming);
        cudaEventCreateWithFlags(&ev0, cudaEventDisableTiming);
        cudaEventCreateWithFlags(&evC, cudaEventDisableTiming);
        cudaGetSymbolAddress((void**)&p_acc1, g_acc1);
    }

    // ---- fork: RNA branch on side stream ----
    cudaEventRecord(evF, 0);
    cudaStreamWaitEvent(sR, evF, 0);

    cudaMemsetAsync(p_acc1, 0, NB * 5 * 256 * sizeof(float), sR);
    k_hist<<<64, 128, 0, sR>>>(global_rna, 3000, 5, 0);
    k_hist<<<64, 128, 0, sR>>>(local_rna, 2998, 65, 1);
    k_transpose<<<3000, 256, 0, sR>>>(c1w, 3000, 0);
    k_transpose<<<2998, 256, 0, sR>>>(c2w, 2998, 1);
    k_acc5s<<<dim3(64, 6), 64, 0, sR>>>();
    k_acc65c<<<dim3(64, 1, 4), 64, 0, sR>>>();
    k_conv<<<dim3(64, 32), 128, (5 * 128 + 5 * 8) * 4, sR>>>(emb1, c1b, 5, 0);
    k_conv<<<dim3(64, 32), 128, (65 * 128 + 65 * 8) * 4, sR>>>(emb2, c2b, 65, 1);
    k_fc_rna<<<dim3(64, 4), 256, 0, sR>>>(fxw, fxb, out);
    cudaEventRecord(evJ, sR);

    // ---- protein branch: CSR build on sC, dense prep on main ----
    k_init<<<196, 256>>>();
    cudaEventRecord(ev0, 0);
    cudaStreamWaitEvent(sC, ev0, 0);

    k_edge_count<<<3125, 256, 0, sC>>>(ei, pw);
    k_dinv<<<196, 256, 0, sC>>>();
    k_scanA<<<SCAN_NBLK, 512, 0, sC>>>();
    k_scanB<<<1, 128, 0, sC>>>();
    k_scanC<<<196, 256, 0, sC>>>();
    k_scatter<<<3125, 256, 0, sC>>>(ei, pw);
    k_selfloop<<<196, 256, 0, sC>>>();
    cudaEventRecord(evC, sC);

    k_gcn_h<<<6250, dim3(36, 8)>>>(pro_x, gcnw);
    cudaStreamWaitEvent(0, evC, 0);
    k_gcn_agg<<<6250, 256>>>(gcnb, bnm, bnv, bnw, bnb);
    k_gat_lr<<<(NN + LR_NPB - 1) / LR_NPB, 264>>>(gwl, gwr);
    k_gat<<<1563, 256>>>(gatt, gb);
    k_pool<<<64, 132>>>(pb);
    k_fc1<<<dim3(64, 4), 256>>>(f1w, f1b);
    k_fc2<<<dim3(64, 2), 256>>>(f2w, f2b, out);

    // ---- join ----
    cudaStreamWaitEvent(0, evJ, 0);
}

// round 9
// speedup vs baseline: 1.7533x; 1.7533x over previous
#include <cuda_runtime.h>
#include <math.h>

#define NN 50000
#define NE 800000
#define E2 850000
#define NB 64
#define SCAN_NBLK 98   // ceil(50000/512)
#define XLS 132        // row stride for xl/xr (528B, 16B-aligned)

// ---------------- scratch ----------------
__device__ float g_deg[NN];
__device__ float g_dinv[NN];
__device__ int   g_indeg[NN];
__device__ int   g_off[NN + 1];
__device__ int   g_bsum[128];
__device__ int   g_cur[NN];
__device__ int   g_ssrc[E2];
__device__ float g_snorm[E2];
__device__ float g_h32[NN * 32];
__device__ float g_h1[NN];
__device__ float g_xpn[NN * 36];
__device__ float g_xl[NN * XLS];
__device__ float g_xr[NN * XLS];
__device__ float g_xp2[NN * 132];
__device__ float g_pool[NB * 132];
__device__ float g_cnt[NB];
__device__ float g_W1t[3000 * 256];
__device__ float g_W2t[2998 * 256];
__device__ float g_acc1[NB * 5 * 256];
__device__ float g_acc2[NB * 65 * 256];
__device__ int   g_pos1[NB * 3000];
__device__ int   g_poff1[NB * 6];
__device__ int   g_pos2[NB * 2998];
__device__ int   g_poff2[NB * 66];
__device__ float g_y1[NB * 3872];
__device__ float g_y2[NB * 3872];
__device__ float g_hid[NB * 1024];

// ---------------- init (protein) ----------------
__global__ void k_init() {
    int i = blockIdx.x * blockDim.x + threadIdx.x;
    if (i < NN) { g_deg[i] = 1.0f; g_indeg[i] = 1; }
    if (i < NB * 132) g_pool[i] = 0.0f;
    if (i < NB) g_cnt[i] = 0.0f;
}

__global__ void k_edge_count(const int* __restrict__ ei, const float* __restrict__ w) {
    int e = blockIdx.x * blockDim.x + threadIdx.x;
    if (e >= NE) return;
    int d = ei[NE + e];
    atomicAdd(&g_deg[d], w[e]);
    atomicAdd(&g_indeg[d], 1);
}

// ---------------- multi-block scan (also computes dinv) ----------------
__global__ void k_scanA() {
    __shared__ int wsum[16];
    int i = blockIdx.x * 512 + threadIdx.x;
    int lane = threadIdx.x & 31, wid = threadIdx.x >> 5;
    if (i < NN) g_dinv[i] = rsqrtf(g_deg[i]);
    int v = (i < NN) ? g_indeg[i] : 0;
    int x = v;
    #pragma unroll
    for (int off = 1; off < 32; off <<= 1) {
        int t = __shfl_up_sync(0xffffffffu, x, off);
        if (lane >= off) x += t;
    }
    if (lane == 31) wsum[wid] = x;
    __syncthreads();
    if (wid == 0) {
        int s = (lane < 16) ? wsum[lane] : 0;
        #pragma unroll
        for (int off = 1; off < 32; off <<= 1) {
            int t = __shfl_up_sync(0xffffffffu, s, off);
            if (lane >= off) s += t;
        }
        if (lane < 16) wsum[lane] = s;
    }
    __syncthreads();
    int pre = (wid > 0) ? wsum[wid - 1] : 0;
    int incl = x + pre;
    if (i < NN) g_off[i] = incl - v;
    if (threadIdx.x == 511) g_bsum[blockIdx.x] = incl;
}

__global__ void k_scanB() {
    __shared__ int wtot[4];
    int t = threadIdx.x;
    int lane = t & 31, wid = t >> 5;
    int v = (t < SCAN_NBLK) ? g_bsum[t] : 0;
    int x = v;
    #pragma unroll
    for (int off = 1; off < 32; off <<= 1) {
        int tt = __shfl_up_sync(0xffffffffu, x, off);
        if (lane >= off) x += tt;
    }
    if (lane == 31) wtot[wid] = x;
    __syncthreads();
    if (t == 0) {
        int run = 0;
        for (int k = 0; k < 4; k++) { int tmp = wtot[k]; wtot[k] = run; run += tmp; }
        g_off[NN] = run;
    }
    __syncthreads();
    int excl = x - v + wtot[wid];
    if (t < SCAN_NBLK) g_bsum[t] = excl;
}

__global__ void k_scanC() {
    int i = blockIdx.x * blockDim.x + threadIdx.x;
    if (i >= NN) return;
    int val = g_off[i] + g_bsum[i >> 9];
    g_off[i] = val;
    g_cur[i] = val;
}

// ---------------- counting-sort scatter (edges + self-loops in one grid) ----------------
__global__ void k_scatter(const int* __restrict__ ei, const float* __restrict__ w) {
    int e = blockIdx.x * blockDim.x + threadIdx.x;
    if (e >= E2) return;
    if (e < NE) {
        int s = ei[e], d = ei[NE + e];
        int p = atomicAdd(&g_cur[d], 1);
        g_ssrc[p] = s;
        g_snorm[p] = g_dinv[s] * w[e] * g_dinv[d];
    } else {
        int i = e - NE;
        int p = atomicAdd(&g_cur[i], 1);
        g_ssrc[p] = i;
        g_snorm[p] = g_dinv[i] * g_dinv[i];
    }
}

// ---------------- GCN transform ----------------
__global__ void k_gcn_h(const float* __restrict__ x, const float* __restrict__ W) {
    __shared__ float Ws[33 * 33];
    __shared__ float xs[8][33];
    int tx = threadIdx.x, ty = threadIdx.y;
    int tid = ty * 36 + tx;
    for (int i = tid; i < 1089; i += 288) Ws[i] = W[i];
    int n = blockIdx.x * 8 + ty;
    if (n < NN && tx < 33) xs[ty][tx] = x[n * 33 + tx];
    __syncthreads();
    if (n >= NN) return;
    if (tx >= 33) return;
    float a = 0.0f;
    #pragma unroll
    for (int k = 0; k < 33; k++) a += xs[ty][k] * Ws[tx * 33 + k];
    if (tx < 32) g_h32[n * 32 + tx] = a;
    else         g_h1[n] = a;
}

// ---------------- GCN aggregation + relu + BN ----------------
__global__ void k_gcn_agg(const float* __restrict__ gcnb, const float* __restrict__ bm,
                          const float* __restrict__ bv, const float* __restrict__ bw,
                          const float* __restrict__ bb) {
    int d = blockIdx.x * 8 + (threadIdx.x >> 5);
    int lane = threadIdx.x & 31;
    if (d >= NN) return;
    int beg = g_off[d], end = g_off[d + 1];
    float a0 = 0.0f, a1 = 0.0f, b0 = 0.0f, b1 = 0.0f;
    int e = beg;
    for (; e + 2 <= end; e += 2) {
        int sA = g_ssrc[e], sB = g_ssrc[e + 1];
        float nA = g_snorm[e], nB = g_snorm[e + 1];
        a0 += g_h32[sA * 32 + lane] * nA;
        b0 += g_h32[sB * 32 + lane] * nB;
        a1 += g_h1[sA] * nA;
        b1 += g_h1[sB] * nB;
    }
    if (e < end) {
        int sA = g_ssrc[e];
        float nA = g_snorm[e];
        a0 += g_h32[sA * 32 + lane] * nA;
        a1 += g_h1[sA] * nA;
    }
    a0 += b0; a1 += b1;
    float c0 = fmaxf(a0 + gcnb[lane], 0.0f);
    float inv0 = bw[lane] * rsqrtf(bv[lane] + 1e-5f);
    g_xpn[d * 36 + lane] = c0 * inv0 + (bb[lane] - bm[lane] * inv0);
    if (lane == 0) {
        float c1 = fmaxf(a1 + gcnb[32], 0.0f);
        float inv1 = bw[32] * rsqrtf(bv[32] + 1e-5f);
        g_xpn[d * 36 + 32] = c1 * inv1 + (bb[32] - bm[32] * inv1);
        g_xpn[d * 36 + 33] = 0.0f;
        g_xpn[d * 36 + 34] = 0.0f;
        g_xpn[d * 36 + 35] = 0.0f;
    }
}

// ---------------- GAT projections ----------------
#define LR_NPB 64
__global__ void k_gat_lr(const float* __restrict__ wl, const float* __restrict__ wr) {
    __shared__ float Wsh[2 * 132 * 33];
    __shared__ float xs[8][33];
    int t = threadIdx.x;  // 0..263
    for (int i = t; i < 4356; i += 264) Wsh[i] = wl[i];
    for (int i = t; i < 4356; i += 264) Wsh[4356 + i] = wr[i];
    __syncthreads();
    int c = t % 132, side = t / 132;
    float wreg[33];
    #pragma unroll
    for (int k = 0; k < 33; k++) wreg[k] = Wsh[side * 4356 + c * 33 + k];
    float* outb = side ? g_xr : g_xl;
    int n0 = blockIdx.x * LR_NPB;
    int n1 = min(n0 + LR_NPB, NN);
    for (int nb = n0; nb < n1; nb += 8) {
        __syncthreads();
        {
            int u = t / 33, k = t % 33;
            int n = nb + u;
            xs[u][k] = (n < NN) ? g_xpn[n * 36 + k] : 0.0f;
        }
        __syncthreads();
        #pragma unroll
        for (int u = 0; u < 8; u++) {
            int n = nb + u;
            if (n < n1) {
                float a = 0.0f;
                #pragma unroll
                for (int k = 0; k < 33; k++) a += wreg[k] * xs[u][k];
                outb[(size_t)n * XLS + c] = a;
            }
        }
    }
}

// ---------------- GATv2: plain softmax, 2 dsts per warp ----------------
__global__ void __launch_bounds__(256) k_gat(const float* __restrict__ att, const float* __restrict__ gb) {
    int lane = threadIdx.x & 31, wid = threadIdx.x >> 5;
    const float4* att4 = (const float4*)att;
    const float4* gb4 = (const float4*)gb;
    float4 z = make_float4(0.f, 0.f, 0.f, 0.f);
    float4 at0 = att4[lane];
    float4 at1 = (lane == 0) ? att4[32] : z;
    int cb = 4 * lane;
    bool hA = cb + 0 < 66, hB = cb + 1 < 66, hC = cb + 2 < 66, hD = cb + 3 < 66;

    int dd[2];
    float4 xr0[2], xr1[2], acc0[2], acc1[2];
    float s0[2], s1[2];
    int beg[2], len[2];
    int maxlen = 0;
    #pragma unroll
    for (int k = 0; k < 2; k++) {
        int d = blockIdx.x * 16 + k * 8 + wid;
        dd[k] = d;
        bool ok = d < NN;
        const float4* xr4 = (const float4*)(g_xr + (size_t)(ok ? d : 0) * XLS);
        xr0[k] = ok ? xr4[lane] : z;
        xr1[k] = (ok && lane == 0) ? xr4[32] : z;
        acc0[k] = z; acc1[k] = z;
        s0[k] = 0.f; s1[k] = 0.f;
        beg[k] = ok ? g_off[d] : 0;
        int e1 = ok ? g_off[d + 1] : 0;
        len[k] = e1 - beg[k];
        maxlen = max(maxlen, len[k]);
    }
    for (int i = 0; i < maxlen; i++) {
        #pragma unroll
        for (int k = 0; k < 2; k++) {
            if (i >= len[k]) continue;   // warp-uniform
            int s = g_ssrc[beg[k] + i];
            const float4* xl4 = (const float4*)(g_xl + (size_t)s * XLS);
            float4 a0 = xl4[lane];
            float4 a1 = (lane == 0) ? xl4[32] : z;
            float p0 = 0.f, p1 = 0.f, v, tt;
            v = a0.x + xr0[k].x; v = v > 0.f ? v : 0.2f * v; tt = v * at0.x; if (hA) p0 += tt; else p1 += tt;
            v = a0.y + xr0[k].y; v = v > 0.f ? v : 0.2f * v; tt = v * at0.y; if (hB) p0 += tt; else p1 += tt;
            v = a0.z + xr0[k].z; v = v > 0.f ? v : 0.2f * v; tt = v * at0.z; if (hC) p0 += tt; else p1 += tt;
            v = a0.w + xr0[k].w; v = v > 0.f ? v : 0.2f * v; tt = v * at0.w; if (hD) p0 += tt; else p1 += tt;
            v = a1.x + xr1[k].x; v = v > 0.f ? v : 0.2f * v; p1 += v * at1.x;
            v = a1.y + xr1[k].y; v = v > 0.f ? v : 0.2f * v; p1 += v * at1.y;
            v = a1.z + xr1[k].z; v = v > 0.f ? v : 0.2f * v; p1 += v * at1.z;
            v = a1.w + xr1[k].w; v = v > 0.f ? v : 0.2f * v; p1 += v * at1.w;
            #pragma unroll
            for (int o = 16; o; o >>= 1) {
                p0 += __shfl_xor_sync(0xffffffffu, p0, o);
                p1 += __shfl_xor_sync(0xffffffffu, p1, o);
            }
            float w0 = __expf(p0), w1 = __expf(p1);
            s0[k] += w0; s1[k] += w1;
            float W0 = hA ? w0 : w1;
            float W1 = hB ? w0 : w1;
            float W2 = hC ? w0 : w1;
            float W3 = hD ? w0 : w1;
            acc0[k].x += W0 * a0.x;
            acc0[k].y += W1 * a0.y;
            acc0[k].z += W2 * a0.z;
            acc0[k].w += W3 * a0.w;
            acc1[k].x += w1 * a1.x;
            acc1[k].y += w1 * a1.y;
            acc1[k].z += w1 * a1.z;
            acc1[k].w += w1 * a1.w;
        }
    }
    float4 gv = gb4[lane];
    float4 gv1 = (lane == 0) ? gb4[32] : z;
    #pragma unroll
    for (int k = 0; k < 2; k++) {
        int d = dd[k];
        if (d >= NN) continue;
        float4 o;
        o.x = fmaxf(acc0[k].x / (hA ? s0[k] : s1[k]) + gv.x, 0.f);
        o.y = fmaxf(acc0[k].y / (hB ? s0[k] : s1[k]) + gv.y, 0.f);
        o.z = fmaxf(acc0[k].z / (hC ? s0[k] : s1[k]) + gv.z, 0.f);
        o.w = fmaxf(acc0[k].w / (hD ? s0[k] : s1[k]) + gv.w, 0.f);
        ((float4*)(g_xp2 + (size_t)d * 132))[lane] = o;
        if (lane == 0) {
            float4 o1;
            o1.x = fmaxf(acc1[k].x / s1[k] + gv1.x, 0.f);
            o1.y = fmaxf(acc1[k].y / s1[k] + gv1.y, 0.f);
            o1.z = fmaxf(acc1[k].z / s1[k] + gv1.z, 0.f);
            o1.w = fmaxf(acc1[k].w / s1[k] + gv1.w, 0.f);
            ((float4*)(g_xp2 + (size_t)d * 132))[32] = o1;
        }
    }
}

// ---------------- mean pool ----------------
__global__ void k_pool(const int* __restrict__ batch) {
    int c = threadIdx.x;  // 0..131
    int start = blockIdx.x * 196;
    int end = min(start + 196, NN);
    if (start >= end) return;
    int cur = batch[start];
    float sum = 0.0f, cnt = 0.0f;
    for (int n = start; n < end; n++) {
        int g = batch[n];
        if (g != cur) {
            atomicAdd(&g_pool[cur * 132 + c], sum);
            if (c == 0) atomicAdd(&g_cnt[cur], cnt);
            sum = 0.0f; cnt = 0.0f; cur = g;
        }
        sum += g_xp2[n * 132 + c];
        cnt += 1.0f;
    }
    atomicAdd(&g_pool[cur * 132 + c], sum);
    if (c == 0) atomicAdd(&g_cnt[cur], cnt);
}

// ---------------- protein MLP head ----------------
__global__ void k_fc1(const float* __restrict__ w, const float* __restrict__ b) {
    int g = blockIdx.x;
    int obase = blockIdx.y * 256;
    __shared__ float m[132];
    if (threadIdx.x < 132) {
        float cnt = fmaxf(g_cnt[g], 1.0f);
        m[threadIdx.x] = g_pool[g * 132 + threadIdx.x] / cnt;
    }
    __syncthreads();
    int wid = threadIdx.x >> 5, lane = threadIdx.x & 31;
    for (int o = obase + wid; o < obase + 256; o += 8) {
        float acc = 0.0f;
        for (int k = lane; k < 132; k += 32) acc += w[o * 132 + k] * m[k];
        #pragma unroll
        for (int off = 16; off; off >>= 1) acc += __shfl_xor_sync(0xffffffffu, acc, off);
        if (lane == 0) g_hid[g * 1024 + o] = fmaxf(acc + b[o], 0.0f);
    }
}

__global__ void k_fc2(const float* __restrict__ w, const float* __restrict__ b, float* __restrict__ out) {
    int g = blockIdx.x;
    int obase = blockIdx.y * 64;
    int wid = threadIdx.x >> 5, lane = threadIdx.x & 31;
    for (int o = obase + wid; o < obase + 64; o += 8) {
        float acc = 0.0f;
        for (int k = lane; k < 1024; k += 32) acc += w[o * 1024 + k] * g_hid[g * 1024 + k];
        #pragma unroll
        for (int off = 16; off; off >>= 1) acc += __shfl_xor_sync(0xffffffffu, acc, off);
        if (lane == 0) out[8192 + g * 128 + o] = acc + b[o];
    }
}

// ---------------- RNA branch ----------------
__global__ void k_transpose(const float* __restrict__ w, int C, int which) {
    float* wt = which ? g_W2t : g_W1t;
    int t = blockIdx.x * blockDim.x + threadIdx.x;
    if (t >= C * 256) return;
    int c = t >> 8, j = t & 255, o = j >> 3, k = j & 7;
    wt[t] = w[o * C * 8 + c * 8 + k];
}

// bucket-sort positions by token per batch; buffers selected INSIDE the kernel
__global__ void k_hist(const int* __restrict__ rna, int C, int V, int which) {
    __shared__ int cnt[66];
    __shared__ int cur[65];
    int* pos = which ? g_pos2 : g_pos1;
    int* poff = which ? g_poff2 : g_poff1;
    int b = blockIdx.x, t = threadIdx.x;  // 128 threads
    for (int i = t; i <= V; i += 128) cnt[i] = 0;
    __syncthreads();
    const int* row = rna + b * C;
    for (int c = t; c < C; c += 128) atomicAdd(&cnt[row[c] + 1], 1);
    __syncthreads();
    if (t == 0) {
        int run = 0;
        for (int v = 0; v <= V; v++) { run += cnt[v]; cnt[v] = run; }
    }
    __syncthreads();
    for (int i = t; i <= V; i += 128) poff[b * (V + 1) + i] = cnt[i];
    if (t < V) cur[t] = cnt[t];
    __syncthreads();
    for (int c = t; c < C; c += 128) {
        int v = row[c];
        int p = atomicAdd(&cur[v], 1);
        pos[b * C + p] = c;
    }
}

// V=5: float4 accumulation over sorted bins; 256 thr = 4 pos-subchunks x 64 j4
__global__ void k_acc5s() {
    int b = blockIdx.x;
    int j4 = threadIdx.x & 63;
    int sub = threadIdx.x >> 6;
    int ci = blockIdx.y * 4 + sub;            // 0..47
    int lo = ci * 63, hi = min(lo + 63, 3000);
    const float4* wt = (const float4*)g_W1t;
    const int* pos = g_pos1 + b * 3000;
    const int* poff = g_poff1 + b * 6;
    float4 z = make_float4(0.f, 0.f, 0.f, 0.f);
    #pragma unroll
    for (int v = 0; v < 5; v++) {
        int p0 = max(poff[v], lo), p1 = min(poff[v + 1], hi);
        if (p0 >= p1) continue;
        float4 aA = z, aB = z, aC = z, aD = z;
        int p = p0;
        for (; p + 4 <= p1; p += 4) {
            int c0 = pos[p], c1 = pos[p + 1], c2 = pos[p + 2], c3 = pos[p + 3];
            float4 w0 = wt[c0 * 64 + j4];
            float4 w1 = wt[c1 * 64 + j4];
            float4 w2 = wt[c2 * 64 + j4];
            float4 w3 = wt[c3 * 64 + j4];
            aA.x += w0.x; aA.y += w0.y; aA.z += w0.z; aA.w += w0.w;
            aB.x += w1.x; aB.y += w1.y; aB.z += w1.z; aB.w += w1.w;
            aC.x += w2.x; aC.y += w2.y; aC.z += w2.z; aC.w += w2.w;
            aD.x += w3.x; aD.y += w3.y; aD.z += w3.z; aD.w += w3.w;
        }
        for (; p < p1; p++) {
            float4 w0 = wt[pos[p] * 64 + j4];
            aA.x += w0.x; aA.y += w0.y; aA.z += w0.z; aA.w += w0.w;
        }
        float* o = g_acc1 + b * 1280 + v * 256 + 4 * j4;
        atomicAdd(o + 0, (aA.x + aB.x) + (aC.x + aD.x));
        atomicAdd(o + 1, (aA.y + aB.y) + (aC.y + aD.y));
        atomicAdd(o + 2, (aA.z + aB.z) + (aC.z + aD.z));
        atomicAdd(o + 3, (aA.w + aB.w) + (aC.w + aD.w));
    }
}

// V=65: float4 accumulation over sorted bins; 256 thr = 4 bins x 64 j4; direct store
__global__ void k_acc65c() {
    int b = blockIdx.x;
    int j4 = threadIdx.x & 63;
    int sub = threadIdx.x >> 6;
    int v = blockIdx.y * 4 + sub;
    if (v >= 65) return;
    const float4* wt = (const float4*)g_W2t;
    const int* pos = g_pos2 + b * 2998;
    const int* poff = g_poff2 + b * 66;
    float4* acc = (float4*)g_acc2;
    float4 z = make_float4(0.f, 0.f, 0.f, 0.f);
    int p0 = poff[v], p1 = poff[v + 1];
    float4 aA = z, aB = z, aC = z, aD = z;
    int p = p0;
    for (; p + 4 <= p1; p += 4) {
        int c0 = pos[p], c1 = pos[p + 1], c2 = pos[p + 2], c3 = pos[p + 3];
        float4 w0 = wt[c0 * 64 + j4];
        float4 w1 = wt[c1 * 64 + j4];
        float4 w2 = wt[c2 * 64 + j4];
        float4 w3 = wt[c3 * 64 + j4];
        aA.x += w0.x; aA.y += w0.y; aA.z += w0.z; aA.w += w0.w;
        aB.x += w1.x; aB.y += w1.y; aB.z += w1.z; aB.w += w1.w;
        aC.x += w2.x; aC.y += w2.y; aC.z += w2.z; aC.w += w2.w;
        aD.x += w3.x; aD.y += w3.y; aD.z += w3.z; aD.w += w3.w;
    }
    for (; p < p1; p++) {
        float4 w0 = wt[pos[p] * 64 + j4];
        aA.x += w0.x; aA.y += w0.y; aA.z += w0.z; aA.w += w0.w;
    }
    float4 r;
    r.x = (aA.x + aB.x) + (aC.x + aD.x);
    r.y = (aA.y + aB.y) + (aC.y + aD.y);
    r.z = (aA.z + aB.z) + (aC.z + aD.z);
    r.w = (aA.w + aB.w) + (aC.w + aD.w);
    acc[b * 4160 + v * 64 + j4] = r;
}

__global__ void k_conv(const float* __restrict__ emb, const float* __restrict__ bias, int V, int which) {
    extern __shared__ float sh[];
    const float* acc = which ? g_acc2 : g_acc1;
    float* y = which ? g_y2 : g_y1;
    float* emb_sh = sh;
    float* acc_sh = sh + V * 128;
    int b = blockIdx.x, o = blockIdx.y, t = threadIdx.x;
    for (int i = t; i < V * 128; i += 128) emb_sh[i] = emb[i];
    for (int i = t; i < V * 8; i += 128) {
        int v = i >> 3, k = i & 7;
        acc_sh[i] = acc[b * V * 256 + v * 256 + o * 8 + k];
    }
    __syncthreads();
    if (t < 121) {
        float s = bias[o];
        for (int v = 0; v < V; v++) {
            #pragma unroll
            for (int k = 0; k < 8; k++) s += acc_sh[v * 8 + k] * emb_sh[v * 128 + t + k];
        }
        y[b * 3872 + o * 121 + t] = s;
    }
}

__global__ void k_fc_rna(const float* __restrict__ w, const float* __restrict__ bias, float* __restrict__ out) {
    __shared__ float ys[3872];
    int b = blockIdx.x;
    int obase = blockIdx.y * 32;
    for (int i = threadIdx.x; i < 3872; i += 256)
        ys[i] = 0.5f * (g_y1[b * 3872 + i] + g_y2[b * 3872 + i]);
    __syncthreads();
    int wid = threadIdx.x >> 5, lane = threadIdx.x & 31;
    for (int dcol = obase + wid; dcol < obase + 32; dcol += 8) {
        float acc = 0.0f;
        for (int i = lane; i < 3872; i += 32) acc += w[dcol * 3872 + i] * ys[i];
        #pragma unroll
        for (int off = 16; off; off >>= 1) acc += __shfl_xor_sync(0xffffffffu, acc, off);
        if (lane == 0) out[b * 128 + dcol] = acc + bias[dcol];
    }
}

// ---------------- launch ----------------
extern "C" void kernel_launch(void* const* d_in, const int* in_sizes, int n_in,
                              void* d_out, int out_size) {
    const int*   global_rna = (const int*)d_in[0];
    const int*   local_rna  = (const int*)d_in[1];
    const float* pro_x      = (const float*)d_in[2];
    const int*   ei         = (const int*)d_in[3];
    const float* pw         = (const float*)d_in[4];
    const int*   pb         = (const int*)d_in[5];
    const float* emb1       = (const float*)d_in[6];
    const float* emb2       = (const float*)d_in[7];
    const float* c1w        = (const float*)d_in[8];
    const float* c1b        = (const float*)d_in[9];
    const float* c2w        = (const float*)d_in[10];
    const float* c2b        = (const float*)d_in[11];
    const float* fxw        = (const float*)d_in[12];
    const float* fxb        = (const float*)d_in[13];
    const float* gcnw       = (const float*)d_in[14];
    const float* gcnb       = (const float*)d_in[15];
    const float* bnm        = (const float*)d_in[16];
    const float* bnv        = (const float*)d_in[17];
    const float* bnw        = (const float*)d_in[18];
    const float* bnb        = (const float*)d_in[19];
    const float* gwl        = (const float*)d_in[20];
    const float* gwr        = (const float*)d_in[21];
    const float* gatt       = (const float*)d_in[22];
    const float* gb         = (const float*)d_in[23];
    const float* f1w        = (const float*)d_in[24];
    const float* f1b        = (const float*)d_in[25];
    const float* f2w        = (const float*)d_in[26];
    const float* f2b        = (const float*)d_in[27];
    float* out = (float*)d_out;

    static cudaStream_t sR = nullptr, sC = nullptr;
    static cudaEvent_t evF = nullptr, evJ = nullptr, ev0 = nullptr, evC = nullptr;
    static float* p_acc1 = nullptr;
    if (!sR) {
        cudaStreamCreateWithFlags(&sR, cudaStreamNonBlocking);
        cudaStreamCreateWithFlags(&sC, cudaStreamNonBlocking);
        cudaEventCreateWithFlags(&evF, cudaEventDisableTiming);
        cudaEventCreateWithFlags(&evJ, cudaEventDisableTiming);
        cudaEventCreateWithFlags(&ev0, cudaEventDisableTiming);
        cudaEventCreateWithFlags(&evC, cudaEventDisableTiming);
        cudaGetSymbolAddress((void**)&p_acc1, g_acc1);
    }

    // ---- fork: RNA branch on side stream ----
    cudaEventRecord(evF, 0);
    cudaStreamWaitEvent(sR, evF, 0);

    cudaMemsetAsync(p_acc1, 0, NB * 5 * 256 * sizeof(float), sR);
    k_hist<<<64, 128, 0, sR>>>(global_rna, 3000, 5, 0);
    k_hist<<<64, 128, 0, sR>>>(local_rna, 2998, 65, 1);
    k_transpose<<<3000, 256, 0, sR>>>(c1w, 3000, 0);
    k_transpose<<<2998, 256, 0, sR>>>(c2w, 2998, 1);
    k_acc5s<<<dim3(64, 12), 256, 0, sR>>>();
    k_acc65c<<<dim3(64, 17), 256, 0, sR>>>();
    k_conv<<<dim3(64, 32), 128, (5 * 128 + 5 * 8) * 4, sR>>>(emb1, c1b, 5, 0);
    k_conv<<<dim3(64, 32), 128, (65 * 128 + 65 * 8) * 4, sR>>>(emb2, c2b, 65, 1);
    k_fc_rna<<<dim3(64, 4), 256, 0, sR>>>(fxw, fxb, out);
    cudaEventRecord(evJ, sR);

    // ---- protein branch: CSR build on sC, dense prep on main ----
    k_init<<<196, 256>>>();
    cudaEventRecord(ev0, 0);
    cudaStreamWaitEvent(sC, ev0, 0);

    k_edge_count<<<3125, 256, 0, sC>>>(ei, pw);
    k_scanA<<<SCAN_NBLK, 512, 0, sC>>>();
    k_scanB<<<1, 128, 0, sC>>>();
    k_scanC<<<196, 256, 0, sC>>>();
    k_scatter<<<(E2 + 255) / 256, 256, 0, sC>>>(ei, pw);
    cudaEventRecord(evC, sC);

    k_gcn_h<<<6250, dim3(36, 8)>>>(pro_x, gcnw);
    cudaStreamWaitEvent(0, evC, 0);
    k_gcn_agg<<<6250, 256>>>(gcnb, bnm, bnv, bnw, bnb);
    k_gat_lr<<<(NN + LR_NPB - 1) / LR_NPB, 264>>>(gwl, gwr);
    k_gat<<<3125, 256>>>(gatt, gb);
    k_pool<<<256, 132>>>(pb);
    k_fc1<<<dim3(64, 4), 256>>>(f1w, f1b);
    k_fc2<<<dim3(64, 2), 256>>>(f2w, f2b, out);

    // ---- join ----
    cudaStreamWaitEvent(0, evJ, 0);
}

// round 13
// speedup vs baseline: 1.7685x; 1.0087x over previous
#include <cuda_runtime.h>
#include <cuda_fp16.h>
#include <math.h>

#define NN 50000
#define NE 800000
#define E2 850000
#define NB 64
#define SCAN_NBLK 98   // ceil(50000/512)

// ---------------- scratch ----------------
__device__ float g_deg[NN];
__device__ float g_dinv[NN];
__device__ int   g_indeg[NN];
__device__ int   g_off[NN + 1];
__device__ int   g_bsum[128];
__device__ int   g_cur[NN];
__device__ int   g_ssrc[E2];
__device__ float g_snorm[E2];
__device__ float g_h32[NN * 32];
__device__ float g_h1[NN];
__device__ float g_xpn[NN * 36];
__device__ __half g_xl[NN * 132];   // fp16 rows, 264B, 8B-aligned
__device__ __half g_xr[NN * 132];
__device__ float g_xp2[NN * 132];
__device__ float g_pool[NB * 132];
__device__ float g_cnt[NB];
__device__ float g_W1t[3000 * 256];
__device__ float g_W2t[2998 * 256];
__device__ float g_acc1[NB * 5 * 256];
__device__ float g_acc2[NB * 65 * 256];
__device__ int   g_pos1[NB * 3000];
__device__ int   g_poff1[NB * 6];
__device__ int   g_pos2[NB * 2998];
__device__ int   g_poff2[NB * 66];
__device__ float g_y1[NB * 3872];
__device__ float g_y2[NB * 3872];
__device__ float g_hid[NB * 1024];

// ---------------- init (protein) ----------------
__global__ void k_init() {
    int i = blockIdx.x * blockDim.x + threadIdx.x;
    if (i < NN) { g_deg[i] = 1.0f; g_indeg[i] = 1; }
    if (i < NB * 132) g_pool[i] = 0.0f;
    if (i < NB) g_cnt[i] = 0.0f;
}

__global__ void k_edge_count(const int* __restrict__ ei, const float* __restrict__ w) {
    int e = blockIdx.x * blockDim.x + threadIdx.x;
    if (e >= NE) return;
    int d = ei[NE + e];
    atomicAdd(&g_deg[d], w[e]);
    atomicAdd(&g_indeg[d], 1);
}

// ---------------- multi-block scan (also computes dinv) ----------------
__global__ void k_scanA() {
    __shared__ int wsum[16];
    int i = blockIdx.x * 512 + threadIdx.x;
    int lane = threadIdx.x & 31, wid = threadIdx.x >> 5;
    if (i < NN) g_dinv[i] = rsqrtf(g_deg[i]);
    int v = (i < NN) ? g_indeg[i] : 0;
    int x = v;
    #pragma unroll
    for (int off = 1; off < 32; off <<= 1) {
        int t = __shfl_up_sync(0xffffffffu, x, off);
        if (lane >= off) x += t;
    }
    if (lane == 31) wsum[wid] = x;
    __syncthreads();
    if (wid == 0) {
        int s = (lane < 16) ? wsum[lane] : 0;
        #pragma unroll
        for (int off = 1; off < 32; off <<= 1) {
            int t = __shfl_up_sync(0xffffffffu, s, off);
            if (lane >= off) s += t;
        }
        if (lane < 16) wsum[lane] = s;
    }
    __syncthreads();
    int pre = (wid > 0) ? wsum[wid - 1] : 0;
    int incl = x + pre;
    if (i < NN) g_off[i] = incl - v;
    if (threadIdx.x == 511) g_bsum[blockIdx.x] = incl;
}

__global__ void k_scanB() {
    __shared__ int wtot[4];
    int t = threadIdx.x;
    int lane = t & 31, wid = t >> 5;
    int v = (t < SCAN_NBLK) ? g_bsum[t] : 0;
    int x = v;
    #pragma unroll
    for (int off = 1; off < 32; off <<= 1) {
        int tt = __shfl_up_sync(0xffffffffu, x, off);
        if (lane >= off) x += tt;
    }
    if (lane == 31) wtot[wid] = x;
    __syncthreads();
    if (t == 0) {
        int run = 0;
        for (int k = 0; k < 4; k++) { int tmp = wtot[k]; wtot[k] = run; run += tmp; }
        g_off[NN] = run;
    }
    __syncthreads();
    int excl = x - v + wtot[wid];
    if (t < SCAN_NBLK) g_bsum[t] = excl;
}

__global__ void k_scanC() {
    int i = blockIdx.x * blockDim.x + threadIdx.x;
    if (i >= NN) return;
    int val = g_off[i] + g_bsum[i >> 9];
    g_off[i] = val;
    g_cur[i] = val;
}

// ---------------- counting-sort scatter (edges + self-loops in one grid) ----------------
__global__ void k_scatter(const int* __restrict__ ei, const float* __restrict__ w) {
    int e = blockIdx.x * blockDim.x + threadIdx.x;
    if (e >= E2) return;
    if (e < NE) {
        int s = ei[e], d = ei[NE + e];
        int p = atomicAdd(&g_cur[d], 1);
        g_ssrc[p] = s;
        g_snorm[p] = g_dinv[s] * w[e] * g_dinv[d];
    } else {
        int i = e - NE;
        int p = atomicAdd(&g_cur[i], 1);
        g_ssrc[p] = i;
        g_snorm[p] = g_dinv[i] * g_dinv[i];
    }
}

// ---------------- GCN transform ----------------
__global__ void k_gcn_h(const float* __restrict__ x, const float* __restrict__ W) {
    __shared__ float Ws[33 * 33];
    __shared__ float xs[8][33];
    int tx = threadIdx.x, ty = threadIdx.y;
    int tid = ty * 36 + tx;
    for (int i = tid; i < 1089; i += 288) Ws[i] = W[i];
    int n = blockIdx.x * 8 + ty;
    if (n < NN && tx < 33) xs[ty][tx] = x[n * 33 + tx];
    __syncthreads();
    if (n >= NN) return;
    if (tx >= 33) return;
    float a = 0.0f;
    #pragma unroll
    for (int k = 0; k < 33; k++) a += xs[ty][k] * Ws[tx * 33 + k];
    if (tx < 32) g_h32[n * 32 + tx] = a;
    else         g_h1[n] = a;
}

// ---------------- GCN aggregation + relu + BN ----------------
__global__ void k_gcn_agg(const float* __restrict__ gcnb, const float* __restrict__ bm,
                          const float* __restrict__ bv, const float* __restrict__ bw,
                          const float* __restrict__ bb) {
    int d = blockIdx.x * 8 + (threadIdx.x >> 5);
    int lane = threadIdx.x & 31;
    if (d >= NN) return;
    int beg = g_off[d], end = g_off[d + 1];
    float a0 = 0.0f, a1 = 0.0f, b0 = 0.0f, b1 = 0.0f;
    int e = beg;
    for (; e + 2 <= end; e += 2) {
        int sA = g_ssrc[e], sB = g_ssrc[e + 1];
        float nA = g_snorm[e], nB = g_snorm[e + 1];
        a0 += g_h32[sA * 32 + lane] * nA;
        b0 += g_h32[sB * 32 + lane] * nB;
        a1 += g_h1[sA] * nA;
        b1 += g_h1[sB] * nB;
    }
    if (e < end) {
        int sA = g_ssrc[e];
        float nA = g_snorm[e];
        a0 += g_h32[sA * 32 + lane] * nA;
        a1 += g_h1[sA] * nA;
    }
    a0 += b0; a1 += b1;
    float c0 = fmaxf(a0 + gcnb[lane], 0.0f);
    float inv0 = bw[lane] * rsqrtf(bv[lane] + 1e-5f);
    g_xpn[d * 36 + lane] = c0 * inv0 + (bb[lane] - bm[lane] * inv0);
    if (lane == 0) {
        float c1 = fmaxf(a1 + gcnb[32], 0.0f);
        float inv1 = bw[32] * rsqrtf(bv[32] + 1e-5f);
        g_xpn[d * 36 + 32] = c1 * inv1 + (bb[32] - bm[32] * inv1);
        g_xpn[d * 36 + 33] = 0.0f;
        g_xpn[d * 36 + 34] = 0.0f;
        g_xpn[d * 36 + 35] = 0.0f;
    }
}

// ---------------- GAT projections (store fp16) ----------------
#define LR_NPB 64
__global__ void k_gat_lr(const float* __restrict__ wl, const float* __restrict__ wr) {
    __shared__ float Wsh[2 * 132 * 33];
    __shared__ float xs[8][33];
    int t = threadIdx.x;  // 0..263
    for (int i = t; i < 4356; i += 264) Wsh[i] = wl[i];
    for (int i = t; i < 4356; i += 264) Wsh[4356 + i] = wr[i];
    __syncthreads();
    int c = t % 132, side = t / 132;
    float wreg[33];
    #pragma unroll
    for (int k = 0; k < 33; k++) wreg[k] = Wsh[side * 4356 + c * 33 + k];
    __half* outb = side ? g_xr : g_xl;
    int n0 = blockIdx.x * LR_NPB;
    int n1 = min(n0 + LR_NPB, NN);
    for (int nb = n0; nb < n1; nb += 8) {
        __syncthreads();
        {
            int u = t / 33, k = t % 33;
            int n = nb + u;
            xs[u][k] = (n < NN) ? g_xpn[n * 36 + k] : 0.0f;
        }
        __syncthreads();
        #pragma unroll
        for (int u = 0; u < 8; u++) {
            int n = nb + u;
            if (n < n1) {
                float a = 0.0f;
                #pragma unroll
                for (int k = 0; k < 33; k++) a += wreg[k] * xs[u][k];
                outb[(size_t)n * 132 + c] = __float2half(a);
            }
        }
    }
}

// load 4 consecutive halves (channels 4*idx..4*idx+3) from a 264B row as float4
__device__ __forceinline__ float4 ld_h4(const uint2* row, int idx) {
    uint2 u = row[idx];
    __half2 hA = *reinterpret_cast<__half2*>(&u.x);
    __half2 hB = *reinterpret_cast<__half2*>(&u.y);
    float2 fA = __half22float2(hA), fB = __half22float2(hB);
    return make_float4(fA.x, fA.y, fB.x, fB.y);
}

// ---------------- GATv2: plain softmax, 2 dsts per warp, fp16 gathers ----------------
__global__ void __launch_bounds__(256) k_gat(const float* __restrict__ att, const float* __restrict__ gb) {
    int lane = threadIdx.x & 31, wid = threadIdx.x >> 5;
    const float4* att4 = (const float4*)att;
    const float4* gb4 = (const float4*)gb;
    float4 z = make_float4(0.f, 0.f, 0.f, 0.f);
    float4 at0 = att4[lane];
    float4 at1 = (lane == 0) ? att4[32] : z;
    int cb = 4 * lane;
    bool hA = cb + 0 < 66, hB = cb + 1 < 66, hC = cb + 2 < 66, hD = cb + 3 < 66;

    int dd[2];
    float4 xr0[2], xr1[2], acc0[2], acc1[2];
    float s0[2], s1[2];
    int beg[2], len[2];
    int maxlen = 0;
    #pragma unroll
    for (int k = 0; k < 2; k++) {
        int d = blockIdx.x * 16 + k * 8 + wid;
        dd[k] = d;
        bool ok = d < NN;
        const uint2* xr2 = (const uint2*)(g_xr + (size_t)(ok ? d : 0) * 132);
        xr0[k] = ok ? ld_h4(xr2, lane) : z;
        xr1[k] = (ok && lane == 0) ? ld_h4(xr2, 32) : z;
        acc0[k] = z; acc1[k] = z;
        s0[k] = 0.f; s1[k] = 0.f;
        beg[k] = ok ? g_off[d] : 0;
        int e1 = ok ? g_off[d + 1] : 0;
        len[k] = e1 - beg[k];
        maxlen = max(maxlen, len[k]);
    }
    for (int i = 0; i < maxlen; i++) {
        #pragma unroll
        for (int k = 0; k < 2; k++) {
            if (i >= len[k]) continue;   // warp-uniform
            int s = g_ssrc[beg[k] + i];
            const uint2* xl2 = (const uint2*)(g_xl + (size_t)s * 132);
            float4 a0 = ld_h4(xl2, lane);
            float4 a1 = (lane == 0) ? ld_h4(xl2, 32) : z;
            float p0 = 0.f, p1 = 0.f, v, tt;
            v = a0.x + xr0[k].x; v = v > 0.f ? v : 0.2f * v; tt = v * at0.x; if (hA) p0 += tt; else p1 += tt;
            v = a0.y + xr0[k].y; v = v > 0.f ? v : 0.2f * v; tt = v * at0.y; if (hB) p0 += tt; else p1 += tt;
            v = a0.z + xr0[k].z; v = v > 0.f ? v : 0.2f * v; tt = v * at0.z; if (hC) p0 += tt; else p1 += tt;
            v = a0.w + xr0[k].w; v = v > 0.f ? v : 0.2f * v; tt = v * at0.w; if (hD) p0 += tt; else p1 += tt;
            v = a1.x + xr1[k].x; v = v > 0.f ? v : 0.2f * v; p1 += v * at1.x;
            v = a1.y + xr1[k].y; v = v > 0.f ? v : 0.2f * v; p1 += v * at1.y;
            v = a1.z + xr1[k].z; v = v > 0.f ? v : 0.2f * v; p1 += v * at1.z;
            v = a1.w + xr1[k].w; v = v > 0.f ? v : 0.2f * v; p1 += v * at1.w;
            #pragma unroll
            for (int o = 16; o; o >>= 1) {
                p0 += __shfl_xor_sync(0xffffffffu, p0, o);
                p1 += __shfl_xor_sync(0xffffffffu, p1, o);
            }
            float w0 = __expf(p0), w1 = __expf(p1);
            s0[k] += w0; s1[k] += w1;
            float W0 = hA ? w0 : w1;
            float W1 = hB ? w0 : w1;
            float W2 = hC ? w0 : w1;
            float W3 = hD ? w0 : w1;
            acc0[k].x += W0 * a0.x;
            acc0[k].y += W1 * a0.y;
            acc0[k].z += W2 * a0.z;
            acc0[k].w += W3 * a0.w;
            acc1[k].x += w1 * a1.x;
            acc1[k].y += w1 * a1.y;
            acc1[k].z += w1 * a1.z;
            acc1[k].w += w1 * a1.w;
        }
    }
    float4 gv = gb4[lane];
    float4 gv1 = (lane == 0) ? gb4[32] : z;
    #pragma unroll
    for (int k = 0; k < 2; k++) {
        int d = dd[k];
        if (d >= NN) continue;
        float4 o;
        o.x = fmaxf(acc0[k].x / (hA ? s0[k] : s1[k]) + gv.x, 0.f);
        o.y = fmaxf(acc0[k].y / (hB ? s0[k] : s1[k]) + gv.y, 0.f);
        o.z = fmaxf(acc0[k].z / (hC ? s0[k] : s1[k]) + gv.z, 0.f);
        o.w = fmaxf(acc0[k].w / (hD ? s0[k] : s1[k]) + gv.w, 0.f);
        ((float4*)(g_xp2 + (size_t)d * 132))[lane] = o;
        if (lane == 0) {
            float4 o1;
            o1.x = fmaxf(acc1[k].x / s1[k] + gv1.x, 0.f);
            o1.y = fmaxf(acc1[k].y / s1[k] + gv1.y, 0.f);
            o1.z = fmaxf(acc1[k].z / s1[k] + gv1.z, 0.f);
            o1.w = fmaxf(acc1[k].w / s1[k] + gv1.w, 0.f);
            ((float4*)(g_xp2 + (size_t)d * 132))[32] = o1;
        }
    }
}

// ---------------- mean pool ----------------
__global__ void k_pool(const int* __restrict__ batch) {
    int c = threadIdx.x;  // 0..131
    int start = blockIdx.x * 196;
    int end = min(start + 196, NN);
    if (start >= end) return;
    int cur = batch[start];
    float sum = 0.0f, cnt = 0.0f;
    for (int n = start; n < end; n++) {
        int g = batch[n];
        if (g != cur) {
            atomicAdd(&g_pool[cur * 132 + c], sum);
            if (c == 0) atomicAdd(&g_cnt[cur], cnt);
            sum = 0.0f; cnt = 0.0f; cur = g;
        }
        sum += g_xp2[n * 132 + c];
        cnt += 1.0f;
    }
    atomicAdd(&g_pool[cur * 132 + c], sum);
    if (c == 0) atomicAdd(&g_cnt[cur], cnt);
}

// ---------------- protein MLP head ----------------
__global__ void k_fc1(const float* __restrict__ w, const float* __restrict__ b) {
    int g = blockIdx.x;
    int obase = blockIdx.y * 256;
    __shared__ float m[132];
    if (threadIdx.x < 132) {
        float cnt = fmaxf(g_cnt[g], 1.0f);
        m[threadIdx.x] = g_pool[g * 132 + threadIdx.x] / cnt;
    }
    __syncthreads();
    int wid = threadIdx.x >> 5, lane = threadIdx.x & 31;
    for (int o = obase + wid; o < obase + 256; o += 8) {
        float acc = 0.0f;
        for (int k = lane; k < 132; k += 32) acc += w[o * 132 + k] * m[k];
        #pragma unroll
        for (int off = 16; off; off >>= 1) acc += __shfl_xor_sync(0xffffffffu, acc, off);
        if (lane == 0) g_hid[g * 1024 + o] = fmaxf(acc + b[o], 0.0f);
    }
}

__global__ void k_fc2(const float* __restrict__ w, const float* __restrict__ b, float* __restrict__ out) {
    int g = blockIdx.x;
    int obase = blockIdx.y * 64;
    int wid = threadIdx.x >> 5, lane = threadIdx.x & 31;
    for (int o = obase + wid; o < obase + 64; o += 8) {
        float acc = 0.0f;
        for (int k = lane; k < 1024; k += 32) acc += w[o * 1024 + k] * g_hid[g * 1024 + k];
        #pragma unroll
        for (int off = 16; off; off >>= 1) acc += __shfl_xor_sync(0xffffffffu, acc, off);
        if (lane == 0) out[8192 + g * 128 + o] = acc + b[o];
    }
}

// ---------------- RNA branch ----------------
// both conv-weight transposes in one grid
__global__ void k_transpose2(const float* __restrict__ w1, const float* __restrict__ w2) {
    int blk = blockIdx.x;
    int which = (blk >= 3000) ? 1 : 0;
    int C = which ? 2998 : 3000;
    const float* w = which ? w2 : w1;
    float* wt = which ? g_W2t : g_W1t;
    int cbase = which ? (blk - 3000) : blk;
    int t = cbase * 256 + threadIdx.x;
    int c = t >> 8, j = t & 255, o = j >> 3, k = j & 7;
    if (c < C) wt[t] = w[o * C * 8 + c * 8 + k];
}

// bucket-sort positions by token per batch; both RNA inputs via grid.y
__global__ void k_hist2(const int* __restrict__ rna1, const int* __restrict__ rna2) {
    __shared__ int cnt[66];
    __shared__ int cur[65];
    int which = blockIdx.y;
    const int* rna = which ? rna2 : rna1;
    int C = which ? 2998 : 3000;
    int V = which ? 65 : 5;
    int* pos = which ? g_pos2 : g_pos1;
    int* poff = which ? g_poff2 : g_poff1;
    int b = blockIdx.x, t = threadIdx.x;  // 128 threads
    for (int i = t; i <= V; i += 128) cnt[i] = 0;
    __syncthreads();
    const int* row = rna + b * C;
    for (int c = t; c < C; c += 128) atomicAdd(&cnt[row[c] + 1], 1);
    __syncthreads();
    if (t == 0) {
        int run = 0;
        for (int v = 0; v <= V; v++) { run += cnt[v]; cnt[v] = run; }
    }
    __syncthreads();
    for (int i = t; i <= V; i += 128) poff[b * (V + 1) + i] = cnt[i];
    if (t < V) cur[t] = cnt[t];
    __syncthreads();
    for (int c = t; c < C; c += 128) {
        int v = row[c];
        int p = atomicAdd(&cur[v], 1);
        pos[b * C + p] = c;
    }
}

// V=5: float4 accumulation over sorted bins; 256 thr = 4 pos-subchunks x 64 j4
__global__ void k_acc5s() {
    int b = blockIdx.x;
    int j4 = threadIdx.x & 63;
    int sub = threadIdx.x >> 6;
    int ci = blockIdx.y * 4 + sub;            // 0..47
    int lo = ci * 63, hi = min(lo + 63, 3000);
    const float4* wt = (const float4*)g_W1t;
    const int* pos = g_pos1 + b * 3000;
    const int* poff = g_poff1 + b * 6;
    float4 z = make_float4(0.f, 0.f, 0.f, 0.f);
    #pragma unroll
    for (int v = 0; v < 5; v++) {
        int p0 = max(poff[v], lo), p1 = min(poff[v + 1], hi);
        if (p0 >= p1) continue;
        float4 aA = z, aB = z, aC = z, aD = z;
        int p = p0;
        for (; p + 4 <= p1; p += 4) {
            int c0 = pos[p], c1 = pos[p + 1], c2 = pos[p + 2], c3 = pos[p + 3];
            float4 w0 = wt[c0 * 64 + j4];
            float4 w1 = wt[c1 * 64 + j4];
            float4 w2 = wt[c2 * 64 + j4];
            float4 w3 = wt[c3 * 64 + j4];
            aA.x += w0.x; aA.y += w0.y; aA.z += w0.z; aA.w += w0.w;
            aB.x += w1.x; aB.y += w1.y; aB.z += w1.z; aB.w += w1.w;
            aC.x += w2.x; aC.y += w2.y; aC.z += w2.z; aC.w += w2.w;
            aD.x += w3.x; aD.y += w3.y; aD.z += w3.z; aD.w += w3.w;
        }
        for (; p < p1; p++) {
            float4 w0 = wt[pos[p] * 64 + j4];
            aA.x += w0.x; aA.y += w0.y; aA.z += w0.z; aA.w += w0.w;
        }
        float* o = g_acc1 + b * 1280 + v * 256 + 4 * j4;
        atomicAdd(o + 0, (aA.x + aB.x) + (aC.x + aD.x));
        atomicAdd(o + 1, (aA.y + aB.y) + (aC.y + aD.y));
        atomicAdd(o + 2, (aA.z + aB.z) + (aC.z + aD.z));
        atomicAdd(o + 3, (aA.w + aB.w) + (aC.w + aD.w));
    }
}

// V=65: float4 accumulation over sorted bins; 256 thr = 4 bins x 64 j4; direct store
__global__ void k_acc65c() {
    int b = blockIdx.x;
    int j4 = threadIdx.x & 63;
    int sub = threadIdx.x >> 6;
    int v = blockIdx.y * 4 + sub;
    if (v >= 65) return;
    const float4* wt = (const float4*)g_W2t;
    const int* pos = g_pos2 + b * 2998;
    const int* poff = g_poff2 + b * 66;
    float4* acc = (float4*)g_acc2;
    float4 z = make_float4(0.f, 0.f, 0.f, 0.f);
    int p0 = poff[v], p1 = poff[v + 1];
    float4 aA = z, aB = z, aC = z, aD = z;
    int p = p0;
    for (; p + 4 <= p1; p += 4) {
        int c0 = pos[p], c1 = pos[p + 1], c2 = pos[p + 2], c3 = pos[p + 3];
        float4 w0 = wt[c0 * 64 + j4];
        float4 w1 = wt[c1 * 64 + j4];
        float4 w2 = wt[c2 * 64 + j4];
        float4 w3 = wt[c3 * 64 + j4];
        aA.x += w0.x; aA.y += w0.y; aA.z += w0.z; aA.w += w0.w;
        aB.x += w1.x; aB.y += w1.y; aB.z += w1.z; aB.w += w1.w;
        aC.x += w2.x; aC.y += w2.y; aC.z += w2.z; aC.w += w2.w;
        aD.x += w3.x; aD.y += w3.y; aD.z += w3.z; aD.w += w3.w;
    }
    for (; p < p1; p++) {
        float4 w0 = wt[pos[p] * 64 + j4];
        aA.x += w0.x; aA.y += w0.y; aA.z += w0.z; aA.w += w0.w;
    }
    float4 r;
    r.x = (aA.x + aB.x) + (aC.x + aD.x);
    r.y = (aA.y + aB.y) + (aC.y + aD.y);
    r.z = (aA.z + aB.z) + (aC.z + aD.z);
    r.w = (aA.w + aB.w) + (aC.w + aD.w);
    acc[b * 4160 + v * 64 + j4] = r;
}

__global__ void k_conv(const float* __restrict__ emb, const float* __restrict__ bias, int V, int which) {
    extern __shared__ float sh[];
    const float* acc = which ? g_acc2 : g_acc1;
    float* y = which ? g_y2 : g_y1;
    float* emb_sh = sh;
    float* acc_sh = sh + V * 128;
    int b = blockIdx.x, o = blockIdx.y, t = threadIdx.x;
    for (int i = t; i < V * 128; i += 128) emb_sh[i] = emb[i];
    for (int i = t; i < V * 8; i += 128) {
        int v = i >> 3, k = i & 7;
        acc_sh[i] = acc[b * V * 256 + v * 256 + o * 8 + k];
    }
    __syncthreads();
    if (t < 121) {
        float s = bias[o];
        for (int v = 0; v < V; v++) {
            #pragma unroll
            for (int k = 0; k < 8; k++) s += acc_sh[v * 8 + k] * emb_sh[v * 128 + t + k];
        }
        y[b * 3872 + o * 121 + t] = s;
    }
}

__global__ void k_fc_rna(const float* __restrict__ w, const float* __restrict__ bias, float* __restrict__ out) {
    __shared__ float ys[3872];
    int b = blockIdx.x;
    int obase = blockIdx.y * 32;
    for (int i = threadIdx.x; i < 3872; i += 256)
        ys[i] = 0.5f * (g_y1[b * 3872 + i] + g_y2[b * 3872 + i]);
    __syncthreads();
    int wid = threadIdx.x >> 5, lane = threadIdx.x & 31;
    for (int dcol = obase + wid; dcol < obase + 32; dcol += 8) {
        float acc = 0.0f;
        for (int i = lane; i < 3872; i += 32) acc += w[dcol * 3872 + i] * ys[i];
        #pragma unroll
        for (int off = 16; off; off >>= 1) acc += __shfl_xor_sync(0xffffffffu, acc, off);
        if (lane == 0) out[b * 128 + dcol] = acc + bias[dcol];
    }
}

// ---------------- launch ----------------
extern "C" void kernel_launch(void* const* d_in, const int* in_sizes, int n_in,
                              void* d_out, int out_size) {
    const int*   global_rna = (const int*)d_in[0];
    const int*   local_rna  = (const int*)d_in[1];
    const float* pro_x      = (const float*)d_in[2];
    const int*   ei         = (const int*)d_in[3];
    const float* pw         = (const float*)d_in[4];
    const int*   pb         = (const int*)d_in[5];
    const float* emb1       = (const float*)d_in[6];
    const float* emb2       = (const float*)d_in[7];
    const float* c1w        = (const float*)d_in[8];
    const float* c1b        = (const float*)d_in[9];
    const float* c2w        = (const float*)d_in[10];
    const float* c2b        = (const float*)d_in[11];
    const float* fxw        = (const float*)d_in[12];
    const float* fxb        = (const float*)d_in[13];
    const float* gcnw       = (const float*)d_in[14];
    const float* gcnb       = (const float*)d_in[15];
    const float* bnm        = (const float*)d_in[16];
    const float* bnv        = (const float*)d_in[17];
    const float* bnw        = (const float*)d_in[18];
    const float* bnb        = (const float*)d_in[19];
    const float* gwl        = (const float*)d_in[20];
    const float* gwr        = (const float*)d_in[21];
    const float* gatt       = (const float*)d_in[22];
    const float* gb         = (const float*)d_in[23];
    const float* f1w        = (const float*)d_in[24];
    const float* f1b        = (const float*)d_in[25];
    const float* f2w        = (const float*)d_in[26];
    const float* f2b        = (const float*)d_in[27];
    float* out = (float*)d_out;

    static cudaStream_t sR = nullptr, sC = nullptr;
    static cudaEvent_t evF = nullptr, evJ = nullptr, ev0 = nullptr, evC = nullptr;
    static float* p_acc1 = nullptr;
    if (!sR) {
        cudaStreamCreateWithFlags(&sR, cudaStreamNonBlocking);
        cudaStreamCreateWithFlags(&sC, cudaStreamNonBlocking);
        cudaEventCreateWithFlags(&evF, cudaEventDisableTiming);
        cudaEventCreateWithFlags(&evJ, cudaEventDisableTiming);
        cudaEventCreateWithFlags(&ev0, cudaEventDisableTiming);
        cudaEventCreateWithFlags(&evC, cudaEventDisableTiming);
        cudaGetSymbolAddress((void**)&p_acc1, g_acc1);
    }

    // ---- fork: RNA branch on side stream ----
    cudaEventRecord(evF, 0);
    cudaStreamWaitEvent(sR, evF, 0);

    cudaMemsetAsync(p_acc1, 0, NB * 5 * 256 * sizeof(float), sR);
    k_hist2<<<dim3(64, 2), 128, 0, sR>>>(global_rna, local_rna);
    k_transpose2<<<5998, 256, 0, sR>>>(c1w, c2w);
    k_acc5s<<<dim3(64, 12), 256, 0, sR>>>();
    k_acc65c<<<dim3(64, 17), 256, 0, sR>>>();
    k_conv<<<dim3(64, 32), 128, (5 * 128 + 5 * 8) * 4, sR>>>(emb1, c1b, 5, 0);
    k_conv<<<dim3(64, 32), 128, (65 * 128 + 65 * 8) * 4, sR>>>(emb2, c2b, 65, 1);
    k_fc_rna<<<dim3(64, 4), 256, 0, sR>>>(fxw, fxb, out);
    cudaEventRecord(evJ, sR);

    // ---- protein branch: CSR build on sC, dense prep on main ----
    k_init<<<196, 256>>>();
    cudaEventRecord(ev0, 0);
    cudaStreamWaitEvent(sC, ev0, 0);

    k_edge_count<<<3125, 256, 0, sC>>>(ei, pw);
    k_scanA<<<SCAN_NBLK, 512, 0, sC>>>();
    k_scanB<<<1, 128, 0, sC>>>();
    k_scanC<<<196, 256, 0, sC>>>();
    k_scatter<<<(E2 + 255) / 256, 256, 0, sC>>>(ei, pw);
    cudaEventRecord(evC, sC);

    k_gcn_h<<<6250, dim3(36, 8)>>>(pro_x, gcnw);
    cudaStreamWaitEvent(0, evC, 0);
    k_gcn_agg<<<6250, 256>>>(gcnb, bnm, bnv, bnw, bnb);
    k_gat_lr<<<(NN + LR_NPB - 1) / LR_NPB, 264>>>(gwl, gwr);
    k_gat<<<3125, 256>>>(gatt, gb);
    k_pool<<<256, 132>>>(pb);
    k_fc1<<<dim3(64, 4), 256>>>(f1w, f1b);
    k_fc2<<<dim3(64, 2), 256>>>(f2w, f2b, out);

    // ---- join ----
    cudaStreamWaitEvent(0, evJ, 0);
}